// round 17
// baseline (speedup 1.0000x reference)
#include <cuda_runtime.h>
#include <cuda_bf16.h>
#include <cuda_fp16.h>
#include <math.h>
#include <stdint.h>

#define DIM 128
#define NL 50000
#define NP 100000
#define N_E_LL 500000
#define N_E_PP 400000
#define N_E_LP 500000
#define N_E_PL 500000

// ------------------------- device scratch (no allocs allowed) -------------------------
__device__ float g_lego0[(size_t)NL * DIM];
__device__ float g_lego1[(size_t)NL * DIM];
__device__ float g_point0[(size_t)NP * DIM];
__device__ float g_point1[(size_t)NP * DIM];
__device__ float g_lego_a[(size_t)NL * DIM];
__device__ float g_point_a[(size_t)NP * DIM];
__device__ float g_q[(size_t)NL * DIM];
__device__ float g_k[(size_t)NL * DIM];
__device__ float g_v[(size_t)NL * DIM];
__device__ float g_hs_pl[(size_t)NP * DIM];
__device__ float g_hs_lp[(size_t)NL * DIM];
__device__ float g_as_l[NP];
__device__ float g_ad_l[NL];
__device__ float g_as_p[NL];
__device__ float g_ad_p[NP];
__device__ float g_C[(size_t)NP * 512];
__device__ float g_B[(size_t)NP * 512];
__device__ float g_eagg[(size_t)NP * DIM];
__device__ float g_wa_l[256];
__device__ float g_wa_p[256];

// pre-split activation shadows (bf16 hi/lo), row-major [m][128]
__device__ __nv_bfloat16 g_xlh0[(size_t)NL * DIM], g_xll0[(size_t)NL * DIM];
__device__ __nv_bfloat16 g_xlh1[(size_t)NL * DIM], g_xll1[(size_t)NL * DIM];
__device__ __nv_bfloat16 g_xph0[(size_t)NP * DIM], g_xpl0[(size_t)NP * DIM];
__device__ __nv_bfloat16 g_xph1[(size_t)NP * DIM], g_xpl1[(size_t)NP * DIM];
__device__ __nv_bfloat16 g_alah[(size_t)NL * DIM], g_alal[(size_t)NL * DIM];
__device__ __nv_bfloat16 g_apah[(size_t)NP * DIM], g_apal[(size_t)NP * DIM];

// sorted-edge infrastructure (per-relation cur/part so sorts can run concurrently)
__device__ int g_rp_ll[NL + 1];
__device__ int g_rp_pl[NL + 1];
__device__ int g_rp_pp[NP + 1];
__device__ int g_rp_lp[NP + 1];
__device__ int g_cur0[NP + 1], g_cur1[NP + 1], g_cur2[NP + 1], g_cur3[NP + 1];
__device__ int g_part0[256], g_part1[256], g_part2[256], g_part3[256];
__device__ int g_ss_ll[N_E_LL], g_sd_ll[N_E_LL];
__device__ int g_ss_pp[N_E_PP], g_sd_pp[N_E_PP];
__device__ int g_ss_lp[N_E_LP], g_sd_lp[N_E_LP];
__device__ int g_ss_pl[N_E_PL], g_sd_pl[N_E_PL];

// pre-split transposed weights (bf16 hi/lo), layout [n][k] k-contiguous
#define OW_Q 0
#define OW_K 16384
#define OW_V 32768
#define OW_S 49152
#define OW_G 65536
#define OW_1D 81920
#define OW_1B 147456
#define W_INST 212992
__device__ __nv_bfloat16 g_wh[(size_t)4 * W_INST];
__device__ __nv_bfloat16 g_wl[(size_t)4 * W_INST];
// W2 transposed fp16, layout [n][512]
__device__ __half g_w2h[(size_t)4 * 65536];

// ------------------------- multi-output GEMM spec -------------------------
struct OutSpec {
    float* base[8];
    const float* bias1[8];
    const float* bias2[8];
    int stride[8];
};

// ------------------------- PTX helpers -------------------------
__device__ __forceinline__ uint32_t smem_u32(const void* p) {
    uint32_t a;
    asm("{ .reg .u64 t; cvta.to.shared.u64 t, %1; cvt.u32.u64 %0, t; }" : "=r"(a) : "l"(p));
    return a;
}
__device__ __forceinline__ void ldsm_x4(uint32_t* r, uint32_t addr) {
    asm volatile("ldmatrix.sync.aligned.m8n8.x4.shared.b16 {%0,%1,%2,%3}, [%4];"
                 : "=r"(r[0]), "=r"(r[1]), "=r"(r[2]), "=r"(r[3]) : "r"(addr));
}
__device__ __forceinline__ void mma_bf16(float* c, const uint32_t* a, const uint32_t* b) {
    asm volatile(
        "mma.sync.aligned.m16n8k16.row.col.f32.bf16.bf16.f32 "
        "{%0,%1,%2,%3}, {%4,%5,%6,%7}, {%8,%9}, {%0,%1,%2,%3};"
        : "+f"(c[0]), "+f"(c[1]), "+f"(c[2]), "+f"(c[3])
        : "r"(a[0]), "r"(a[1]), "r"(a[2]), "r"(a[3]), "r"(b[0]), "r"(b[1]));
}
__device__ __forceinline__ void mma_f16(float* c, const uint32_t* a, const uint32_t* b) {
    asm volatile(
        "mma.sync.aligned.m16n8k16.row.col.f32.f16.f16.f32 "
        "{%0,%1,%2,%3}, {%4,%5,%6,%7}, {%8,%9}, {%0,%1,%2,%3};"
        : "+f"(c[0]), "+f"(c[1]), "+f"(c[2]), "+f"(c[3])
        : "r"(a[0]), "r"(a[1]), "r"(a[2]), "r"(a[3]), "r"(b[0]), "r"(b[1]));
}
__device__ __forceinline__ uint32_t f2h2(float a, float b) {
    __half2 h = __floats2half2_rn(a, b);
    return *reinterpret_cast<uint32_t*>(&h);
}

// ------------------------- small helpers -------------------------
__device__ __forceinline__ void atomicMaxF(float* addr, float val) {
    if (val >= 0.0f) atomicMax((int*)addr, __float_as_int(val));
    else             atomicMin((unsigned int*)addr, (unsigned int)__float_as_int(val));
}

__global__ void fill_kernel(float* __restrict__ p, float v, int n) {
    int i = blockIdx.x * blockDim.x + threadIdx.x;
    if (i < n) p[i] = v;
}
__global__ void fill_int_kernel(int* __restrict__ p, int v, int n) {
    int i = blockIdx.x * blockDim.x + threadIdx.x;
    if (i < n) p[i] = v;
}
__global__ void copy_int_kernel(int* __restrict__ d, const int* __restrict__ s, int n) {
    int i = blockIdx.x * blockDim.x + threadIdx.x;
    if (i < n) d[i] = s[i];
}

// elementwise Markstein presplit: x -> bf16 hi + bf16 lo (vectorized 4/thread)
__global__ void presplit_kernel(const float* __restrict__ x, __nv_bfloat16* __restrict__ hi,
                                __nv_bfloat16* __restrict__ lo, int n4) {
    int i = blockIdx.x * 256 + threadIdx.x;
    if (i >= n4) return;
    float4 f = ((const float4*)x)[i];
    __nv_bfloat16 h0 = __float2bfloat16(f.x), h1 = __float2bfloat16(f.y);
    __nv_bfloat16 h2 = __float2bfloat16(f.z), h3 = __float2bfloat16(f.w);
    __nv_bfloat162 hp0 = __halves2bfloat162(h0, h1), hp1 = __halves2bfloat162(h2, h3);
    __nv_bfloat16 l0 = __float2bfloat16(f.x - __bfloat162float(h0));
    __nv_bfloat16 l1 = __float2bfloat16(f.y - __bfloat162float(h1));
    __nv_bfloat16 l2 = __float2bfloat16(f.z - __bfloat162float(h2));
    __nv_bfloat16 l3 = __float2bfloat16(f.w - __bfloat162float(h3));
    __nv_bfloat162 lp0 = __halves2bfloat162(l0, l1), lp1 = __halves2bfloat162(l2, l3);
    ((uint2*)hi)[i] = make_uint2(*(uint32_t*)&hp0, *(uint32_t*)&hp1);
    ((uint2*)lo)[i] = make_uint2(*(uint32_t*)&lp0, *(uint32_t*)&lp1);
}

// ------------------------- counting sort by dst -------------------------
__global__ void hist_kernel(const int* __restrict__ dst, int E, int* __restrict__ cnt) {
    int e = blockIdx.x * blockDim.x + threadIdx.x;
    if (e < E) atomicAdd(&cnt[dst[e]], 1);
}
__global__ void scan_block_kernel(int* __restrict__ data, int* __restrict__ part, int n) {
    __shared__ int sh[1024];
    int i = blockIdx.x * 1024 + threadIdx.x;
    int x = (i < n) ? data[i] : 0;
    sh[threadIdx.x] = x;
    __syncthreads();
    for (int o = 1; o < 1024; o <<= 1) {
        int t = (threadIdx.x >= o) ? sh[threadIdx.x - o] : 0;
        __syncthreads();
        sh[threadIdx.x] += t;
        __syncthreads();
    }
    if (i < n) data[i] = sh[threadIdx.x] - x;
    if (threadIdx.x == 1023) part[blockIdx.x] = sh[1023];
}
__global__ void scan_part_kernel(int* __restrict__ part, int nb) {
    __shared__ int sh[1024];
    int x = (threadIdx.x < nb) ? part[threadIdx.x] : 0;
    sh[threadIdx.x] = x;
    __syncthreads();
    for (int o = 1; o < 1024; o <<= 1) {
        int t = (threadIdx.x >= o) ? sh[threadIdx.x - o] : 0;
        __syncthreads();
        sh[threadIdx.x] += t;
        __syncthreads();
    }
    if (threadIdx.x < nb) part[threadIdx.x] = sh[threadIdx.x] - x;
}
__global__ void scan_add_kernel(int* __restrict__ data, const int* __restrict__ part, int n) {
    int i = blockIdx.x * 1024 + threadIdx.x;
    if (i < n) data[i] += part[blockIdx.x];
}
__global__ void scatter_kernel(const int* __restrict__ src, const int* __restrict__ dst, int E,
                               int* __restrict__ cur, int* __restrict__ ssrc, int* __restrict__ sdst) {
    int e = blockIdx.x * blockDim.x + threadIdx.x;
    if (e >= E) return;
    int d = dst[e];
    int pos = atomicAdd(&cur[d], 1);
    ssrc[pos] = src[e];
    sdst[pos] = d;
}

// ------------------------- weight prep -------------------------
__global__ void split_wT_kernel(const float* __restrict__ W, int K, int N,
                                __nv_bfloat16* __restrict__ hiT, __nv_bfloat16* __restrict__ loT) {
    int idx = blockIdx.x * 256 + threadIdx.x;
    if (idx >= K * N) return;
    int k = idx / N, n = idx - k * N;
    float x = W[idx];
    __nv_bfloat16 h = __float2bfloat16(x);
    __nv_bfloat16 l = __float2bfloat16(x - __bfloat162float(h));
    hiT[(size_t)n * K + k] = h;
    loT[(size_t)n * K + k] = l;
}
__global__ void split_w1d_kernel(const float* __restrict__ W1,
                                 __nv_bfloat16* __restrict__ hiT, __nv_bfloat16* __restrict__ loT) {
    int idx = blockIdx.x * 256 + threadIdx.x;
    if (idx >= 128 * 512) return;
    int k = idx >> 9, n = idx & 511;
    float x = W1[idx] - W1[idx + 128 * 512];
    __nv_bfloat16 h = __float2bfloat16(x);
    __nv_bfloat16 l = __float2bfloat16(x - __bfloat162float(h));
    hiT[(size_t)n * 128 + k] = h;
    loT[(size_t)n * 128 + k] = l;
}
__global__ void split_w2_h_kernel(const float* __restrict__ W2, __half* __restrict__ outT) {
    int idx = blockIdx.x * 256 + threadIdx.x;
    if (idx >= 512 * 128) return;
    int k = idx >> 7, n = idx & 127;
    outT[(size_t)n * 512 + k] = __float2half_rn(W2[idx]);
}

__global__ void wa_kernel(const float* __restrict__ W, const float* __restrict__ a_s,
                          const float* __restrict__ a_d, float* __restrict__ wa) {
    int r = threadIdx.x;
    const float* av = (r < 128) ? a_s : a_d;
    int rr = r & 127;
    float s = 0.0f;
    for (int c = 0; c < 128; c++) s = fmaf(W[rr * 128 + c], av[c], s);
    wa[r] = s;
}

__global__ void gemv_dot_kernel(const float* __restrict__ X, const float* __restrict__ w,
                                float* __restrict__ out, int N) {
    int i = (blockIdx.x * blockDim.x + threadIdx.x) >> 5;
    if (i >= N) return;
    int lane = threadIdx.x & 31;
    float4 xa = ((const float4*)(X + (size_t)i * DIM))[lane];
    float4 wv = ((const float4*)w)[lane];
    float p = xa.x * wv.x + xa.y * wv.y + xa.z * wv.z + xa.w * wv.w;
#pragma unroll
    for (int o = 16; o; o >>= 1) p += __shfl_down_sync(0xffffffffu, p, o);
    if (lane == 0) out[i] = p;
}

// ------------------------- mma.sync node GEMM (bf16 3-pass, pre-split A, multi-output) -------------------------
#define SA_G 272
#define OAH 0
#define OAL 34816
#define OBH 69632
#define OBL 104448
#define GEMM_SMEM 139264

__global__ __launch_bounds__(256, 1)
void gemm_tc(const __nv_bfloat16* __restrict__ Ahi, const __nv_bfloat16* __restrict__ Alo,
             const __nv_bfloat16* __restrict__ WhiT, const __nv_bfloat16* __restrict__ WloT,
             OutSpec spec, int M) {
    extern __shared__ __align__(16) char smem[];
    const uint32_t sbase = smem_u32(smem);
    const int tid = threadIdx.x, lane = tid & 31, wid = tid >> 5;
    const int bm = blockIdx.y * 128, bn = blockIdx.x * 128;

    // ---- A tile: straight copies from pre-split activations ----
#pragma unroll
    for (int it = 0; it < 8; it++) {
        int task = tid + it * 256;           // 2048 tasks: 128 m x 16 chunks
        int m = task >> 4, c = task & 15;
        int gm = bm + m;
        uint4 hi = make_uint4(0, 0, 0, 0), lo = make_uint4(0, 0, 0, 0);
        if (gm < M) {
            hi = *(const uint4*)(Ahi + (size_t)gm * 128 + c * 8);
            lo = *(const uint4*)(Alo + (size_t)gm * 128 + c * 8);
        }
        uint32_t off = (uint32_t)m * SA_G + (uint32_t)c * 16;
        *(uint4*)(smem + OAH + off) = hi;
        *(uint4*)(smem + OAL + off) = lo;
    }
    // ---- B tile: straight copies from pre-split transposed weights ----
#pragma unroll
    for (int it = 0; it < 8; it++) {
        int task = tid + it * 256;
        int n = task >> 4, c = task & 15;
        uint32_t off = (uint32_t)n * SA_G + (uint32_t)c * 16;
        *(uint4*)(smem + OBH + off) = *(const uint4*)(WhiT + (size_t)(bn + n) * 128 + c * 8);
        *(uint4*)(smem + OBL + off) = *(const uint4*)(WloT + (size_t)(bn + n) * 128 + c * 8);
    }
    __syncthreads();

    const int wm = (wid & 3) * 32, wn = (wid >> 2) * 64;
    const int g = lane >> 3, lr = lane & 7;
    const uint32_t aoff = (uint32_t)((g & 1) * 8 + lr) * SA_G + (uint32_t)(g >> 1) * 16;
    const uint32_t boff = (uint32_t)((g >> 1) * 8 + lr) * SA_G + (uint32_t)(g & 1) * 16;

    float acc[2][8][4];
#pragma unroll
    for (int i = 0; i < 2; i++)
#pragma unroll
        for (int j = 0; j < 8; j++)
#pragma unroll
            for (int r = 0; r < 4; r++) acc[i][j][r] = 0.0f;

#pragma unroll
    for (int pass = 0; pass < 3; pass++) {
        uint32_t Ab = sbase + (pass == 2 ? OAL : OAH) + (uint32_t)wm * SA_G + aoff;
        uint32_t Bb = sbase + (pass == 1 ? OBL : OBH) + (uint32_t)wn * SA_G + boff;
#pragma unroll
        for (int s = 0; s < 8; s++) {
            uint32_t a[2][4], b[4][4];
#pragma unroll
            for (int i = 0; i < 2; i++) ldsm_x4(a[i], Ab + i * (16 * SA_G) + s * 32);
#pragma unroll
            for (int j = 0; j < 4; j++) ldsm_x4(b[j], Bb + j * (16 * SA_G) + s * 32);
#pragma unroll
            for (int i = 0; i < 2; i++)
#pragma unroll
                for (int j = 0; j < 8; j++)
                    mma_bf16(acc[i][j], a[i], &b[j >> 1][(j & 1) * 2]);
        }
    }

    float* base = spec.base[blockIdx.x];
    const float* bb1 = spec.bias1[blockIdx.x];
    const float* bb2 = spec.bias2[blockIdx.x];
    const int stride = spec.stride[blockIdx.x];
    const int qq = lane >> 2, idx = lane & 3;
#pragma unroll
    for (int i = 0; i < 2; i++) {
        int gr0 = bm + wm + i * 16 + qq;
#pragma unroll
        for (int j = 0; j < 8; j++) {
            int gcl = wn + j * 8 + idx * 2;
            float bb0 = 0.0f, bv1 = 0.0f;
            if (bb1) { bb0 += bb1[gcl]; bv1 += bb1[gcl + 1]; }
            if (bb2) { bb0 += bb2[gcl]; bv1 += bb2[gcl + 1]; }
            if (gr0 < M)
                *(float2*)(base + (size_t)gr0 * stride + gcl) =
                    make_float2(acc[i][j][0] + bb0, acc[i][j][1] + bv1);
            int gr1 = gr0 + 8;
            if (gr1 < M)
                *(float2*)(base + (size_t)gr1 * stride + gcl) =
                    make_float2(acc[i][j][2] + bb0, acc[i][j][3] + bv1);
        }
    }
}

// ------------------------- fp16 single-pass EdgeConv MLP + segment max -------------------------
#define SE_G 144
#define EH0 1024
#define EH1 19456
#define EW0 37888
#define EW1 56320
#define EDGE_SMEM 74752

__global__ __launch_bounds__(256, 1)
void edge_tc(const float* __restrict__ Cn, const float* __restrict__ Bn,
             const int* __restrict__ src, const int* __restrict__ dst, int E,
             const __half* __restrict__ W2T, const float* __restrict__ b2,
             float* __restrict__ agg) {
    extern __shared__ __align__(16) char smem[];
    const uint32_t sbase = smem_u32(smem);
    const int tid = threadIdx.x, lane = tid & 31, wid = tid >> 5;
    const int e0 = blockIdx.x * 128;
    int* sS = (int*)(smem);
    int* sD = (int*)(smem + 512);

    if (tid < 128) {
        int e = e0 + tid;
        sS[tid] = (e < E) ? src[e] : 0;
        sD[tid] = (e < E) ? dst[e] : 0;
    }
    __syncthreads();

    const int wm = (wid & 3) * 32, wn = (wid >> 2) * 64;
    const int g = lane >> 3, lr = lane & 7;
    const uint32_t aoff = (uint32_t)((g & 1) * 8 + lr) * SE_G + (uint32_t)(g >> 1) * 16;
    const uint32_t boff = (uint32_t)((g >> 1) * 8 + lr) * SE_G + (uint32_t)(g & 1) * 16;

    float acc[2][8][4];
#pragma unroll
    for (int i = 0; i < 2; i++)
#pragma unroll
        for (int j = 0; j < 8; j++)
#pragma unroll
            for (int r = 0; r < 4; r++) acc[i][j][r] = 0.0f;

    const int HB[2] = {EH0, EH1};
    const int WB[2] = {EW0, EW1};

    auto load_chunk = [&](int kc, int pb) {
        char* wdst = smem + WB[pb];
        const __half* wsrc = W2T + kc * 64;
#pragma unroll
        for (int it = 0; it < 4; it++) {
            int task = tid + it * 256;
            int n = task >> 3, c = task & 7;
            *(uint4*)(wdst + n * SE_G + c * 16) = *(const uint4*)(wsrc + (size_t)n * 512 + c * 8);
        }
        char* hdst = smem + HB[pb];
#pragma unroll
        for (int it = 0; it < 4; it++) {
            int task = tid + it * 256;
            int e = task >> 3, k8 = task & 7;
            const float4* pc = (const float4*)(Cn + (size_t)sD[e] * 512 + kc * 64 + k8 * 8);
            const float4* pb4 = (const float4*)(Bn + (size_t)sS[e] * 512 + kc * 64 + k8 * 8);
            float4 c0v = pc[0], c1v = pc[1], b0v = pb4[0], b1v = pb4[1];
            uint4 u;
            u.x = f2h2(fmaxf(c0v.x + b0v.x, 0.f), fmaxf(c0v.y + b0v.y, 0.f));
            u.y = f2h2(fmaxf(c0v.z + b0v.z, 0.f), fmaxf(c0v.w + b0v.w, 0.f));
            u.z = f2h2(fmaxf(c1v.x + b1v.x, 0.f), fmaxf(c1v.y + b1v.y, 0.f));
            u.w = f2h2(fmaxf(c1v.z + b1v.z, 0.f), fmaxf(c1v.w + b1v.w, 0.f));
            *(uint4*)(hdst + e * SE_G + k8 * 16) = u;
        }
    };

    load_chunk(0, 0);
    __syncthreads();

    for (int kc = 0; kc < 8; kc++) {
        int pb = kc & 1;
        if (kc < 7) load_chunk(kc + 1, pb ^ 1);
        uint32_t Ab = sbase + HB[pb] + (uint32_t)wm * SE_G + aoff;
        uint32_t Bb = sbase + WB[pb] + (uint32_t)wn * SE_G + boff;
#pragma unroll
        for (int s = 0; s < 4; s++) {
            uint32_t a[2][4], b[4][4];
#pragma unroll
            for (int i = 0; i < 2; i++) ldsm_x4(a[i], Ab + i * (16 * SE_G) + s * 32);
#pragma unroll
            for (int j = 0; j < 4; j++) ldsm_x4(b[j], Bb + j * (16 * SE_G) + s * 32);
#pragma unroll
            for (int i = 0; i < 2; i++)
#pragma unroll
                for (int j = 0; j < 8; j++)
                    mma_f16(acc[i][j], a[i], &b[j >> 1][(j & 1) * 2]);
        }
        __syncthreads();
    }

    const int qq = lane >> 2, idx = lane & 3;
#pragma unroll
    for (int i = 0; i < 2; i++) {
#pragma unroll
        for (int half = 0; half < 2; half++) {
            int el = wm + i * 16 + half * 8 + qq;
            if (e0 + el >= E) continue;
            float* ag = agg + (size_t)sD[el] * 128;
#pragma unroll
            for (int j = 0; j < 8; j++) {
                int c = wn + j * 8 + idx * 2;
                atomicMaxF(&ag[c],     acc[i][j][half * 2 + 0] + b2[c]);
                atomicMaxF(&ag[c + 1], acc[i][j][half * 2 + 1] + b2[c + 1]);
            }
        }
    }
}

// ------------------------- fused online-softmax attention (warp per dst node) -------------------------
__global__ void trans_fused_kernel(const int* __restrict__ rp, const int* __restrict__ ssrc,
                                   const float* __restrict__ q, const float* __restrict__ k,
                                   const float* __restrict__ v, float* __restrict__ out, int N) {
    int node = (blockIdx.x * blockDim.x + threadIdx.x) >> 5;
    if (node >= N) return;
    int lane = threadIdx.x & 31;
    int beg = rp[node], end = rp[node + 1];
    if (beg == end) return;
    float4 qv = ((const float4*)(q + (size_t)node * DIM))[lane];
    float m = -INFINITY, s = 0.f, ax = 0.f, ay = 0.f, az = 0.f, aw = 0.f;
    int e = beg;
    for (; e + 2 <= end; e += 2) {
        int s0 = ssrc[e], s1 = ssrc[e + 1];
        float4 k0 = ((const float4*)(k + (size_t)s0 * DIM))[lane];
        float4 k1 = ((const float4*)(k + (size_t)s1 * DIM))[lane];
        float4 v0 = ((const float4*)(v + (size_t)s0 * DIM))[lane];
        float4 v1 = ((const float4*)(v + (size_t)s1 * DIM))[lane];
        float p0 = k0.x * qv.x + k0.y * qv.y + k0.z * qv.z + k0.w * qv.w;
        float p1 = k1.x * qv.x + k1.y * qv.y + k1.z * qv.z + k1.w * qv.w;
#pragma unroll
        for (int o = 16; o; o >>= 1) {
            p0 += __shfl_xor_sync(0xffffffffu, p0, o);
            p1 += __shfl_xor_sync(0xffffffffu, p1, o);
        }
        p0 *= 0.08838834764831845f;
        p1 *= 0.08838834764831845f;
        float nm = fmaxf(m, fmaxf(p0, p1));
        float scl = expf(m - nm), a0 = expf(p0 - nm), a1 = expf(p1 - nm);
        s = s * scl + a0 + a1;
        ax = ax * scl + a0 * v0.x + a1 * v1.x;
        ay = ay * scl + a0 * v0.y + a1 * v1.y;
        az = az * scl + a0 * v0.z + a1 * v1.z;
        aw = aw * scl + a0 * v0.w + a1 * v1.w;
        m = nm;
    }
    if (e < end) {
        int s0 = ssrc[e];
        float4 k0 = ((const float4*)(k + (size_t)s0 * DIM))[lane];
        float4 v0 = ((const float4*)(v + (size_t)s0 * DIM))[lane];
        float p0 = k0.x * qv.x + k0.y * qv.y + k0.z * qv.z + k0.w * qv.w;
#pragma unroll
        for (int o = 16; o; o >>= 1) p0 += __shfl_xor_sync(0xffffffffu, p0, o);
        p0 *= 0.08838834764831845f;
        float nm = fmaxf(m, p0);
        float scl = expf(m - nm), a0 = expf(p0 - nm);
        s = s * scl + a0;
        ax = ax * scl + a0 * v0.x;
        ay = ay * scl + a0 * v0.y;
        az = az * scl + a0 * v0.z;
        aw = aw * scl + a0 * v0.w;
    }
    float inv = 1.0f / (s + 1e-16f);
    float4* op = (float4*)(out + (size_t)node * DIM) + lane;
    float4 c = *op;
    c.x += ax * inv; c.y += ay * inv; c.z += az * inv; c.w += aw * inv;
    *op = c;
}

__global__ void gat_fused_kernel(const int* __restrict__ rp, const int* __restrict__ ssrc,
                                 const float* __restrict__ as_, const float* __restrict__ ad_,
                                 const float* __restrict__ hs, float* __restrict__ out, int N) {
    int node = (blockIdx.x * blockDim.x + threadIdx.x) >> 5;
    if (node >= N) return;
    int lane = threadIdx.x & 31;
    int beg = rp[node], end = rp[node + 1];
    if (beg == end) return;
    float adv = ad_[node];
    float m = -INFINITY, s = 0.f, ax = 0.f, ay = 0.f, az = 0.f, aw = 0.f;
    int e = beg;
    for (; e + 2 <= end; e += 2) {
        int s0 = ssrc[e], s1 = ssrc[e + 1];
        float p0 = as_[s0] + adv, p1 = as_[s1] + adv;
        p0 = (p0 > 0.f) ? p0 : 0.2f * p0;
        p1 = (p1 > 0.f) ? p1 : 0.2f * p1;
        float4 v0 = ((const float4*)(hs + (size_t)s0 * DIM))[lane];
        float4 v1 = ((const float4*)(hs + (size_t)s1 * DIM))[lane];
        float nm = fmaxf(m, fmaxf(p0, p1));
        float scl = expf(m - nm), a0 = expf(p0 - nm), a1 = expf(p1 - nm);
        s = s * scl + a0 + a1;
        ax = ax * scl + a0 * v0.x + a1 * v1.x;
        ay = ay * scl + a0 * v0.y + a1 * v1.y;
        az = az * scl + a0 * v0.z + a1 * v1.z;
        aw = aw * scl + a0 * v0.w + a1 * v1.w;
        m = nm;
    }
    if (e < end) {
        int s0 = ssrc[e];
        float p0 = as_[s0] + adv;
        p0 = (p0 > 0.f) ? p0 : 0.2f * p0;
        float4 v0 = ((const float4*)(hs + (size_t)s0 * DIM))[lane];
        float nm = fmaxf(m, p0);
        float scl = expf(m - nm), a0 = expf(p0 - nm);
        s = s * scl + a0;
        ax = ax * scl + a0 * v0.x;
        ay = ay * scl + a0 * v0.y;
        az = az * scl + a0 * v0.z;
        aw = aw * scl + a0 * v0.w;
    }
    float inv = 1.0f / (s + 1e-16f);
    float4* op = (float4*)(out + (size_t)node * DIM) + lane;
    float4 c = *op;
    c.x += ax * inv; c.y += ay * inv; c.z += az * inv; c.w += aw * inv;
    *op = c;
}

__global__ void finalize_max_kernel(const float* __restrict__ agg, const float* __restrict__ gbias,
                                    float* __restrict__ out, int n) {
    int i = blockIdx.x * blockDim.x + threadIdx.x;
    if (i >= n) return;
    float v = agg[i];
    if (!isfinite(v)) v = 0.0f;
    if (gbias) v += gbias[i & (DIM - 1)];
    out[i] = v;
}

// ------------------------- host orchestration -------------------------
static inline int ceil_div(int a, int b) { return (a + b - 1) / b; }

extern "C" void kernel_launch(void* const* d_in, const int* in_sizes, int n_in,
                              void* d_out, int out_size) {
    const float* in_xl = (const float*)d_in[0];
    const float* in_xp = (const float*)d_in[1];
    const float* tWq = (const float*)d_in[2];
    const float* tbq = (const float*)d_in[3];
    const float* tWk = (const float*)d_in[4];
    const float* tbk = (const float*)d_in[5];
    const float* tWv = (const float*)d_in[6];
    const float* tbv = (const float*)d_in[7];
    const float* tWs = (const float*)d_in[8];
    const float* tbs = (const float*)d_in[9];
    const float* eW1 = (const float*)d_in[10];
    const float* eb1 = (const float*)d_in[11];
    const float* eW2 = (const float*)d_in[12];
    const float* eb2 = (const float*)d_in[13];
    const float* gW  = (const float*)d_in[14];
    const float* gAs = (const float*)d_in[15];
    const float* gAd = (const float*)d_in[16];
    const float* gb  = (const float*)d_in[17];
    const int* ll_src = (const int*)d_in[18];
    const int* ll_dst = (const int*)d_in[19];
    const int* pp_src = (const int*)d_in[20];
    const int* pp_dst = (const int*)d_in[21];
    const int* lp_src = (const int*)d_in[22];
    const int* lp_dst = (const int*)d_in[23];
    const int* pl_src = (const int*)d_in[24];
    const int* pl_dst = (const int*)d_in[25];

    cudaFuncSetAttribute(gemm_tc, cudaFuncAttributeMaxDynamicSharedMemorySize, GEMM_SMEM);
    cudaFuncSetAttribute(edge_tc, cudaFuncAttributeMaxDynamicSharedMemorySize, EDGE_SMEM);

    float *lx0, *lx1, *px0, *px1, *la, *pa, *q, *k, *v;
    float *hs_pl, *hs_lp, *as_l, *ad_l, *as_p, *ad_p, *Cb, *Bb, *ea, *wa_l, *wa_p;
    cudaGetSymbolAddress((void**)&lx0, g_lego0);
    cudaGetSymbolAddress((void**)&lx1, g_lego1);
    cudaGetSymbolAddress((void**)&px0, g_point0);
    cudaGetSymbolAddress((void**)&px1, g_point1);
    cudaGetSymbolAddress((void**)&la, g_lego_a);
    cudaGetSymbolAddress((void**)&pa, g_point_a);
    cudaGetSymbolAddress((void**)&q, g_q);
    cudaGetSymbolAddress((void**)&k, g_k);
    cudaGetSymbolAddress((void**)&v, g_v);
    cudaGetSymbolAddress((void**)&hs_pl, g_hs_pl);
    cudaGetSymbolAddress((void**)&hs_lp, g_hs_lp);
    cudaGetSymbolAddress((void**)&as_l, g_as_l);
    cudaGetSymbolAddress((void**)&ad_l, g_ad_l);
    cudaGetSymbolAddress((void**)&as_p, g_as_p);
    cudaGetSymbolAddress((void**)&ad_p, g_ad_p);
    cudaGetSymbolAddress((void**)&Cb, g_C);
    cudaGetSymbolAddress((void**)&Bb, g_B);
    cudaGetSymbolAddress((void**)&ea, g_eagg);
    cudaGetSymbolAddress((void**)&wa_l, g_wa_l);
    cudaGetSymbolAddress((void**)&wa_p, g_wa_p);

    __nv_bfloat16 *xlh[2], *xll[2], *xph[2], *xpl[2], *alah, *alal, *apah, *apal;
    cudaGetSymbolAddress((void**)&xlh[0], g_xlh0);
    cudaGetSymbolAddress((void**)&xll[0], g_xll0);
    cudaGetSymbolAddress((void**)&xlh[1], g_xlh1);
    cudaGetSymbolAddress((void**)&xll[1], g_xll1);
    cudaGetSymbolAddress((void**)&xph[0], g_xph0);
    cudaGetSymbolAddress((void**)&xpl[0], g_xpl0);
    cudaGetSymbolAddress((void**)&xph[1], g_xph1);
    cudaGetSymbolAddress((void**)&xpl[1], g_xpl1);
    cudaGetSymbolAddress((void**)&alah, g_alah);
    cudaGetSymbolAddress((void**)&alal, g_alal);
    cudaGetSymbolAddress((void**)&apah, g_apah);
    cudaGetSymbolAddress((void**)&apal, g_apal);

    __half* w2h;
    cudaGetSymbolAddress((void**)&w2h, g_w2h);

    int *rp_ll, *rp_pl, *rp_pp, *rp_lp;
    int *cur0, *cur1, *cur2, *cur3, *part0, *part1, *part2, *part3;
    int *ss_ll, *sd_ll, *ss_pp, *sd_pp, *ss_lp, *sd_lp, *ss_pl, *sd_pl;
    cudaGetSymbolAddress((void**)&rp_ll, g_rp_ll);
    cudaGetSymbolAddress((void**)&rp_pl, g_rp_pl);
    cudaGetSymbolAddress((void**)&rp_pp, g_rp_pp);
    cudaGetSymbolAddress((void**)&rp_lp, g_rp_lp);
    cudaGetSymbolAddress((void**)&cur0, g_cur0);
    cudaGetSymbolAddress((void**)&cur1, g_cur1);
    cudaGetSymbolAddress((void**)&cur2, g_cur2);
    cudaGetSymbolAddress((void**)&cur3, g_cur3);
    cudaGetSymbolAddress((void**)&part0, g_part0);
    cudaGetSymbolAddress((void**)&part1, g_part1);
    cudaGetSymbolAddress((void**)&part2, g_part2);
    cudaGetSymbolAddress((void**)&part3, g_part3);
    cudaGetSymbolAddress((void**)&ss_ll, g_ss_ll);
    cudaGetSymbolAddress((void**)&sd_ll, g_sd_ll);
    cudaGetSymbolAddress((void**)&ss_pp, g_ss_pp);
    cudaGetSymbolAddress((void**)&sd_pp, g_sd_pp);
    cudaGetSymbolAddress((void**)&ss_lp, g_ss_lp);
    cudaGetSymbolAddress((void**)&sd_lp, g_sd_lp);
    cudaGetSymbolAddress((void**)&ss_pl, g_ss_pl);
    cudaGetSymbolAddress((void**)&sd_pl, g_sd_pl);

    __nv_bfloat16 *wh, *wl;
    cudaGetSymbolAddress((void**)&wh, g_wh);
    cudaGetSymbolAddress((void**)&wl, g_wl);

    // ---- streams + events ----
    cudaStream_t sL, sP;
    cudaStreamCreateWithFlags(&sL, cudaStreamNonBlocking);
    cudaStreamCreateWithFlags(&sP, cudaStreamNonBlocking);
    cudaEvent_t evF0, evF1, eL[2], eP[2];
    cudaEventCreateWithFlags(&evF0, cudaEventDisableTiming);
    cudaEventCreateWithFlags(&evF1, cudaEventDisableTiming);
    for (int i = 0; i < 2; i++) {
        cudaEventCreateWithFlags(&eL[i], cudaEventDisableTiming);
        cudaEventCreateWithFlags(&eP[i], cudaEventDisableTiming);
    }

    auto sort_rel = [&](const int* src, const int* dst, int E, int Nn, int* rp,
                        int* ssrc, int* sdst, int* curb, int* partb, cudaStream_t st) {
        int n1 = Nn + 1;
        fill_int_kernel<<<ceil_div(n1, 256), 256, 0, st>>>(rp, 0, n1);
        hist_kernel<<<ceil_div(E, 256), 256, 0, st>>>(dst, E, rp);
        int nb = ceil_div(n1, 1024);
        scan_block_kernel<<<nb, 1024, 0, st>>>(rp, partb, n1);
        scan_part_kernel<<<1, 1024, 0, st>>>(partb, nb);
        scan_add_kernel<<<nb, 1024, 0, st>>>(rp, partb, n1);
        copy_int_kernel<<<ceil_div(n1, 256), 256, 0, st>>>(curb, rp, n1);
        scatter_kernel<<<ceil_div(E, 256), 256, 0, st>>>(src, dst, E, curb, ssrc, sdst);
    };

    auto gemm_multi = [&](const __nv_bfloat16* Ah, const __nv_bfloat16* Al, size_t woff,
                          const OutSpec& sp, int M, int nblk, cudaStream_t st) {
        dim3 gr(nblk, ceil_div(M, 128));
        gemm_tc<<<gr, 256, GEMM_SMEM, st>>>(Ah, Al, wh + woff, wl + woff, sp, M);
    };
    auto presplit = [&](const float* x, __nv_bfloat16* hi, __nv_bfloat16* lo, int n,
                        cudaStream_t st) {
        presplit_kernel<<<ceil_div(n / 4, 256), 256, 0, st>>>(x, hi, lo, n / 4);
    };

    // ======== prologue ========
    cudaEventRecord(evF0, 0);
    cudaStreamWaitEvent(sL, evF0, 0);
    cudaStreamWaitEvent(sP, evF0, 0);
    sort_rel(ll_src, ll_dst, N_E_LL, NL, rp_ll, ss_ll, sd_ll, cur0, part0, sL);
    sort_rel(pl_src, pl_dst, N_E_PL, NL, rp_pl, ss_pl, sd_pl, cur1, part1, sL);
    sort_rel(pp_src, pp_dst, N_E_PP, NP, rp_pp, ss_pp, sd_pp, cur2, part2, sP);
    sort_rel(lp_src, lp_dst, N_E_LP, NP, rp_lp, ss_lp, sd_lp, cur3, part3, sP);
    for (int i = 0; i < 4; i++) {
        size_t o = (size_t)i * W_INST;
        split_wT_kernel<<<64, 256>>>(tWq + (size_t)i * 16384, 128, 128, wh + o + OW_Q, wl + o + OW_Q);
        split_wT_kernel<<<64, 256>>>(tWk + (size_t)i * 16384, 128, 128, wh + o + OW_K, wl + o + OW_K);
        split_wT_kernel<<<64, 256>>>(tWv + (size_t)i * 16384, 128, 128, wh + o + OW_V, wl + o + OW_V);
        split_wT_kernel<<<64, 256>>>(tWs + (size_t)i * 16384, 128, 128, wh + o + OW_S, wl + o + OW_S);
        split_wT_kernel<<<64, 256>>>(gW  + (size_t)i * 16384, 128, 128, wh + o + OW_G, wl + o + OW_G);
        split_w1d_kernel<<<256, 256>>>(eW1 + (size_t)i * 131072, wh + o + OW_1D, wl + o + OW_1D);
        split_wT_kernel<<<256, 256>>>(eW1 + (size_t)i * 131072 + 65536, 128, 512,
                                      wh + o + OW_1B, wl + o + OW_1B);
        split_w2_h_kernel<<<256, 256>>>(eW2 + (size_t)i * 65536, w2h + (size_t)i * 65536);
    }
    cudaMemcpyAsync(lx0, in_xl, sizeof(float) * (size_t)NL * DIM, cudaMemcpyDeviceToDevice, 0);
    cudaMemcpyAsync(px0, in_xp, sizeof(float) * (size_t)NP * DIM, cudaMemcpyDeviceToDevice, 0);
    presplit(lx0, xlh[0], xll[0], NL * DIM, 0);
    presplit(px0, xph[0], xpl[0], NP * DIM, 0);
    cudaEventRecord(evF1, 0);
    cudaStreamWaitEvent(sL, evF1, 0);
    cudaStreamWaitEvent(sP, evF1, 0);

    float* lbuf[2] = {lx0, lx1};
    float* pbuf[2] = {px0, px1};

    for (int layer = 0; layer < 2; layer++) {
        const int iA = 2 * layer, iB = 2 * layer + 1;
        const int i_lp = 2 * layer, i_pl = 2 * layer + 1;
        const size_t oA = (size_t)iA * W_INST, oB = (size_t)iB * W_INST;
        const size_t oLP = (size_t)i_lp * W_INST, oPL = (size_t)i_pl * W_INST;
        const int cu = layer & 1, nx = (layer + 1) & 1;
        const float* lin = lbuf[cu];
        const float* pin = pbuf[cu];
        float* lout = lbuf[nx];
        float* pout = pbuf[nx];

        // ======== chain-L (lego) on sL: own-chain first, pin-consumers after eP wait ========
        {
            OutSpec sp{};
            sp.base[0] = q;  sp.bias1[0] = tbq + iA * 128; sp.stride[0] = 128;
            sp.base[1] = k;  sp.bias1[1] = tbk + iA * 128; sp.stride[1] = 128;
            sp.base[2] = v;  sp.bias1[2] = tbv + iA * 128; sp.stride[2] = 128;
            sp.base[3] = la; sp.bias1[3] = tbs + iA * 128; sp.bias2[3] = gb + i_pl * 128;
            sp.stride[3] = 128;
            gemm_multi(xlh[cu], xll[cu], oA + OW_Q, sp, NL, 4, sL);
        }
        trans_fused_kernel<<<ceil_div(NL, 8), 256, 0, sL>>>(rp_ll, ss_ll, q, k, v, la, NL);
        wa_kernel<<<1, 256, 0, sL>>>(gW + (size_t)i_pl * 16384, gAs + i_pl * 128,
                                     gAd + i_pl * 128, wa_l);
        gemv_dot_kernel<<<ceil_div(NL, 8), 256, 0, sL>>>(lin, wa_l + 128, ad_l, NL);
        if (layer > 0) cudaStreamWaitEvent(sL, eP[layer - 1], 0);  // pin ready
        {
            OutSpec sp{};
            sp.base[0] = hs_pl; sp.stride[0] = 128;
            gemm_multi(xph[cu], xpl[cu], oPL + OW_G, sp, NP, 1, sL);
        }
        gemv_dot_kernel<<<ceil_div(NP, 8), 256, 0, sL>>>(pin, wa_l, as_l, NP);
        gat_fused_kernel<<<ceil_div(NL, 8), 256, 0, sL>>>(rp_pl, ss_pl, as_l, ad_l, hs_pl, la, NL);
        presplit(la, alah, alal, NL * DIM, sL);
        {
            OutSpec sp{};
            sp.base[0] = q;    sp.bias1[0] = tbq + iB * 128; sp.stride[0] = 128;
            sp.base[1] = k;    sp.bias1[1] = tbk + iB * 128; sp.stride[1] = 128;
            sp.base[2] = v;    sp.bias1[2] = tbv + iB * 128; sp.stride[2] = 128;
            sp.base[3] = lout; sp.bias1[3] = tbs + iB * 128; sp.stride[3] = 128;
            gemm_multi(alah, alal, oB + OW_Q, sp, NL, 4, sL);
        }
        trans_fused_kernel<<<ceil_div(NL, 8), 256, 0, sL>>>(rp_ll, ss_ll, q, k, v, lout, NL);
        presplit(lout, xlh[nx], xll[nx], NL * DIM, sL);
        cudaEventRecord(eL[layer], sL);

        // ======== chain-P (point) on sP: own-chain first, lin-consumers after eL wait ========
        {
            OutSpec sp{};
            for (int i = 0; i < 4; i++) {
                sp.base[i] = Cb + i * 128; sp.stride[i] = 512;
                sp.bias1[i] = eb1 + iA * 512 + i * 128;
            }
            for (int i = 4; i < 8; i++) { sp.base[i] = Bb + (i - 4) * 128; sp.stride[i] = 512; }
            gemm_multi(xph[cu], xpl[cu], oA + OW_1D, sp, NP, 8, sP);
        }
        fill_kernel<<<ceil_div(NP * DIM, 256), 256, 0, sP>>>(ea, -INFINITY, NP * DIM);
        edge_tc<<<ceil_div(N_E_PP, 128), 256, EDGE_SMEM, sP>>>(Cb, Bb, ss_pp, sd_pp, N_E_PP,
                                                               w2h + (size_t)iA * 65536,
                                                               eb2 + iA * 128, ea);
        finalize_max_kernel<<<ceil_div(NP * DIM, 256), 256, 0, sP>>>(ea, gb + i_lp * 128, pa,
                                                                     NP * DIM);
        wa_kernel<<<1, 256, 0, sP>>>(gW + (size_t)i_lp * 16384, gAs + i_lp * 128,
                                     gAd + i_lp * 128, wa_p);
        gemv_dot_kernel<<<ceil_div(NP, 8), 256, 0, sP>>>(pin, wa_p + 128, ad_p, NP);
        if (layer > 0) cudaStreamWaitEvent(sP, eL[layer - 1], 0);  // lin ready
        {
            OutSpec sp{};
            sp.base[0] = hs_lp; sp.stride[0] = 128;
            gemm_multi(xlh[cu], xll[cu], oLP + OW_G, sp, NL, 1, sP);
        }
        gemv_dot_kernel<<<ceil_div(NL, 8), 256, 0, sP>>>(lin, wa_p, as_p, NL);
        gat_fused_kernel<<<ceil_div(NP, 8), 256, 0, sP>>>(rp_lp, ss_lp, as_p, ad_p, hs_lp, pa, NP);
        presplit(pa, apah, apal, NP * DIM, sP);
        {
            OutSpec sp{};
            for (int i = 0; i < 4; i++) {
                sp.base[i] = Cb + i * 128; sp.stride[i] = 512;
                sp.bias1[i] = eb1 + iB * 512 + i * 128;
            }
            for (int i = 4; i < 8; i++) { sp.base[i] = Bb + (i - 4) * 128; sp.stride[i] = 512; }
            gemm_multi(apah, apal, oB + OW_1D, sp, NP, 8, sP);
        }
        fill_kernel<<<ceil_div(NP * DIM, 256), 256, 0, sP>>>(ea, -INFINITY, NP * DIM);
        edge_tc<<<ceil_div(N_E_PP, 128), 256, EDGE_SMEM, sP>>>(Cb, Bb, ss_pp, sd_pp, N_E_PP,
                                                               w2h + (size_t)iB * 65536,
                                                               eb2 + iB * 128, ea);
        finalize_max_kernel<<<ceil_div(NP * DIM, 256), 256, 0, sP>>>(ea, nullptr, pout, NP * DIM);
        if (layer + 1 < 2) presplit(pout, xph[nx], xpl[nx], NP * DIM, sP);
        cudaEventRecord(eP[layer], sP);
    }

    cudaStreamWaitEvent(0, eL[1], 0);
    cudaStreamWaitEvent(0, eP[1], 0);
    float* out = (float*)d_out;
    cudaMemcpyAsync(out, lx0, sizeof(float) * (size_t)NL * DIM, cudaMemcpyDeviceToDevice, 0);
    cudaMemcpyAsync(out + (size_t)NL * DIM, px0, sizeof(float) * (size_t)NP * DIM,
                    cudaMemcpyDeviceToDevice, 0);

    cudaStreamDestroy(sL);
    cudaStreamDestroy(sP);
    cudaEventDestroy(evF0);
    cudaEventDestroy(evF1);
    for (int i = 0; i < 2; i++) {
        cudaEventDestroy(eL[i]);
        cudaEventDestroy(eP[i]);
    }
}